// round 8
// baseline (speedup 1.0000x reference)
#include <cuda_runtime.h>

// BrockHommes: B=8192 rows, T=4096 strictly-sequential steps, one row per
// thread. KEY CHANGE this round: 2 warps per SMSP (block=256 -> 8 warps,
// wid%4 => exactly 2 per SMSP; grid=32, one block per SM). Per-warp issue is
// in-order, so a lone warp pays every exposed MUFU/scoreboard wait as bubbles
// (~162 cyc/step measured vs ~75 chain). With a co-resident warp the arbiter
// fills those bubbles cycle-granularly -> each warp runs near chain speed.
//
// Algebra (exact up to fp rounding):
//  * softmax shift-invariance, shifted by regime-0 exponent:
//      w_k = p_k/den, p_0 = 1, p_k = 2^(sL*(d_k-d_0)), d_k = g_k*x3 + b_k,
//      sL = beta*log2e*(x1 - R*x2)   (common -R*x2 term cancels).
//  * E_k = d_k - d_0 computed directly: E_k = (g_k-g0)*x3 + (c_k-c0).
//  * overflow guard: a_k = fmin(sL*E_k, 88).
//  * recurrence closed through the reciprocal:
//      sL_next = (bl*num)*rd + pre2,  pre2 = fma(bl, es, -bl*R*x1).

#define B_CONST 8192
#define T_CONST 4096

__device__ __forceinline__ float ex2a(float x){float y;asm("ex2.approx.f32 %0, %1;":"=f"(y):"f"(x));return y;}
__device__ __forceinline__ float rcpa(float x){float y;asm("rcp.approx.f32 %0, %1;":"=f"(y):"f"(x));return y;}

// One step.
// In:  ES = eps_t*sigma/R; X1,X2 = x_{t-1},x_{t-2}; SL carried;
//      E1..E3 = d_k - d_0 (built from x_{t-3}).
// Out: XT = x_t; SLN = next sL; F1..F3 = next step's E (built from X2).
#define BH_STEP(ES, X1, X2, SL, E1,E2,E3, XT, SLN, F1,F2,F3) \
  { \
    /* ---- critical path head ---- */ \
    float q1 = SL * E1; \
    float q2 = SL * E2; \
    float q3 = SL * E3; \
    float a1 = fminf(q1, 88.0f); \
    float a2 = fminf(q2, 88.0f); \
    float a3 = fminf(q3, 88.0f); \
    float p1 = ex2a(a1); \
    float p2 = ex2a(a2); \
    float p3 = ex2a(a3); \
    /* ---- shadow work ---- */ \
    float m0 = fmaf(gi0, X1, bi0); \
    float m1 = fmaf(gi1, X1, bi1); \
    float m2 = fmaf(gi2, X1, bi2); \
    float m3 = fmaf(gi3, X1, bi3); \
    float pre2 = fmaf(bl, ES, nblR * X1); \
    F1 = fmaf(gd1, X2, cd1); \
    F2 = fmaf(gd2, X2, cd2); \
    F3 = fmaf(gd3, X2, cd3); \
    /* ---- arrival-ordered linear reductions ---- */ \
    float den = ((1.0f + p1) + p2) + p3; \
    float num = fmaf(p3, m3, fmaf(p2, m2, fmaf(p1, m1, m0))); \
    float rd = rcpa(den); \
    float blnum = bl * num; \
    XT  = fmaf(num, rd, ES); \
    SLN = fmaf(blnum, rd, pre2); \
  }

__global__ void __launch_bounds__(256, 1)
bh_kernel(const float* __restrict__ theta,
          const float* __restrict__ eps,
          float* __restrict__ out)
{
    const int b = blockIdx.x * 256 + threadIdx.x;   // 0..8191

    const float* th = theta + (size_t)b * 11;
    const float L2E = 1.44269504088896340736f;

    const float g0 = th[1], g1 = th[2], g2 = th[3], g3 = th[4];
    const float c0 = th[5], c1 = th[6], c2 = th[7], c3 = th[8];
    const float R    = 1.0f + th[10];
    const float iR   = 1.0f / R;                  // one-time accurate div
    const float bl   = th[0] * L2E;               // beta * log2(e)
    const float nblR = -bl * R;
    const float sg   = th[9] * iR;                // sigma / R
    const float gi0 = g0 * iR, gi1 = g1 * iR, gi2 = g2 * iR, gi3 = g3 * iR;
    const float bi0 = c0 * iR, bi1 = c1 * iR, bi2 = c2 * iR, bi3 = c3 * iR;
    // E-prep constants: E_k = (g_k - g0)*x3 + (c_k - c0)
    const float gd1 = g1 - g0, gd2 = g2 - g0, gd3 = g3 - g0;
    const float cd1 = c1 - c0, cd2 = c2 - c0, cd3 = c3 - c0;

    const float4* ep4 = reinterpret_cast<const float4*>(eps + (size_t)b * T_CONST);
    float4*       o4  = reinterpret_cast<float4*>(out + (size_t)b * T_CONST);
    const int T4 = T_CONST / 4;

    // carried state
    float x1 = 0.f, x2 = 0.f;
    float sL = 0.f;
    // E-set for the first step (x3 = 0)
    float e1 = cd1, e2 = cd2, e3 = cd3;

    // distance-2 prefetch
    float4 bufA = ep4[0];
    float4 bufB = ep4[1];

    for (int i = 0; i < T4; ++i) {
        float4 ev = bufA;
        bufA = bufB;
        int nidx = (i + 2 < T4) ? (i + 2) : (T4 - 1);
        bufB = ep4[nidx];

        float es0 = ev.x * sg, es1 = ev.y * sg, es2 = ev.z * sg, es3 = ev.w * sg;

        float xt0, xt1, xt2, xt3;
        float sLb, sLc, sLd, sLe;
        float u1, u2, u3;     // E-set after step0
        float v1, v2, v3;     // after step1
        float w1, w2, w3;     // after step2

        BH_STEP(es0, x1,  x2,  sL,  e1,e2,e3, xt0, sLb, u1,u2,u3);
        BH_STEP(es1, xt0, x1,  sLb, u1,u2,u3, xt1, sLc, v1,v2,v3);
        BH_STEP(es2, xt1, xt0, sLc, v1,v2,v3, xt2, sLd, w1,w2,w3);
        BH_STEP(es3, xt2, xt1, sLd, w1,w2,w3, xt3, sLe, e1,e2,e3);

        x2 = xt2;
        x1 = xt3;
        sL = sLe;

        o4[i] = make_float4(xt0, xt1, xt2, xt3);
    }
}

extern "C" void kernel_launch(void* const* d_in, const int* in_sizes, int n_in,
                              void* d_out, int out_size)
{
    const float* theta = (const float*)d_in[0];   // (B, 11) float32
    const float* eps   = (const float*)d_in[1];   // (B, T)  float32
    float*       out   = (float*)d_out;           // (B, T)  float32

    bh_kernel<<<B_CONST / 256, 256>>>(theta, eps, out);
}

// round 9
// speedup vs baseline: 1.2463x; 1.2463x over previous
#include <cuda_runtime.h>

// BrockHommes: B=8192 rows, T=4096 strictly-sequential steps, one row per
// thread, grid=256 x block=32 (HW spreads 1-warp blocks across SMSPs; R8
// proved co-residency SLOWS each warp, and wall = T * per-warp step time).
//
// Algebra (exact up to fp rounding):
//  * softmax shift-invariance, shifted by regime-0 exponent:
//      w_k = p_k/den, p_0 = 1, p_k = 2^(U * E'_k),
//      E'_k = beta*log2e*(d_k - d_0) built from pre-scaled constants:
//      E'_k = bgd_k*x3 + bcd_k,  bgd_k = bl*(g_k-g0), bcd_k = bl*(c_k-c0),
//      U = x1 - R*x2   (bl absorbed into E' => no sL, no blnum, no pre2).
//  * overflow guard: a_k = fmin(q_k, 88).
//  * recurrence closed through the reciprocal:
//      U' = fma(num, rd, esr),  esr = fma(-R, x1, ES)  (shadow),
//      xt = fma(num, rd, ES).
// Chain: U -> q -> clamp -> ex2(x3, rt8) -> den -> rcp -> U'  (~68 cyc model).

#define B_CONST 8192
#define T_CONST 4096

__device__ __forceinline__ float ex2a(float x){float y;asm("ex2.approx.f32 %0, %1;":"=f"(y):"f"(x));return y;}
__device__ __forceinline__ float rcpa(float x){float y;asm("rcp.approx.f32 %0, %1;":"=f"(y):"f"(x));return y;}

// One step.
// In:  ES = eps_t*sigma/R; X1,X2 = x_{t-1},x_{t-2}; U carried;
//      E1..E3 = bl*(d_k-d_0) (built from x_{t-3}).
// Out: XT = x_t; UN = next U; F1..F3 = next step's E (built from X2).
#define BH_STEP(ES, X1, X2, U, E1,E2,E3, XT, UN, F1,F2,F3) \
  { \
    /* ---- critical path head ---- */ \
    float q1 = U * E1; \
    float q2 = U * E2; \
    float q3 = U * E3; \
    float a1 = fminf(q1, 88.0f); \
    float a2 = fminf(q2, 88.0f); \
    float a3 = fminf(q3, 88.0f); \
    float p1 = ex2a(a1); \
    float p2 = ex2a(a2); \
    float p3 = ex2a(a3); \
    /* ---- shadow work (fills MUFU latency) ---- */ \
    float m0 = fmaf(gi0, X1, bi0); \
    float m1 = fmaf(gi1, X1, bi1); \
    float m2 = fmaf(gi2, X1, bi2); \
    float m3 = fmaf(gi3, X1, bi3); \
    float esr = fmaf(nR, X1, ES); \
    F1 = fmaf(bgd1, X2, bcd1); \
    F2 = fmaf(bgd2, X2, bcd2); \
    F3 = fmaf(bgd3, X2, bcd3); \
    /* ---- arrival-ordered reductions ---- */ \
    float den = ((1.0f + p1) + p2) + p3; \
    float num = fmaf(p3, m3, fmaf(p2, m2, fmaf(p1, m1, m0))); \
    float rd = rcpa(den); \
    XT = fmaf(num, rd, ES); \
    UN = fmaf(num, rd, esr); \
  }

__global__ void __launch_bounds__(32, 1)
bh_kernel(const float* __restrict__ theta,
          const float* __restrict__ eps,
          float* __restrict__ out)
{
    const int b = blockIdx.x * 32 + threadIdx.x;   // 0..8191

    const float* th = theta + (size_t)b * 11;
    const float L2E = 1.44269504088896340736f;

    const float g0 = th[1], g1 = th[2], g2 = th[3], g3 = th[4];
    const float c0 = th[5], c1 = th[6], c2 = th[7], c3 = th[8];
    const float R    = 1.0f + th[10];
    const float iR   = 1.0f / R;                  // one-time accurate div
    const float bl   = th[0] * L2E;               // beta * log2(e)
    const float nR   = -R;
    const float sg   = th[9] * iR;                // sigma / R
    const float gi0 = g0 * iR, gi1 = g1 * iR, gi2 = g2 * iR, gi3 = g3 * iR;
    const float bi0 = c0 * iR, bi1 = c1 * iR, bi2 = c2 * iR, bi3 = c3 * iR;
    // E'-prep constants: E'_k = bl*(g_k - g0)*x3 + bl*(c_k - c0)
    const float bgd1 = bl * (g1 - g0), bgd2 = bl * (g2 - g0), bgd3 = bl * (g3 - g0);
    const float bcd1 = bl * (c1 - c0), bcd2 = bl * (c2 - c0), bcd3 = bl * (c3 - c0);

    const float4* ep4 = reinterpret_cast<const float4*>(eps + (size_t)b * T_CONST);
    float4*       o4  = reinterpret_cast<float4*>(out + (size_t)b * T_CONST);
    const int T4 = T_CONST / 4;

    // carried state
    float x1 = 0.f, x2 = 0.f;
    float U  = 0.f;                               // x1 - R*x2 = 0 at t=0
    // E'-set for the first step (x3 = 0)
    float e1 = bcd1, e2 = bcd2, e3 = bcd3;

    // distance-2 prefetch
    float4 bufA = ep4[0];
    float4 bufB = ep4[1];

    for (int i = 0; i < T4; ++i) {
        float4 ev = bufA;
        bufA = bufB;
        int nidx = (i + 2 < T4) ? (i + 2) : (T4 - 1);
        bufB = ep4[nidx];

        float es0 = ev.x * sg, es1 = ev.y * sg, es2 = ev.z * sg, es3 = ev.w * sg;

        float xt0, xt1, xt2, xt3;
        float Ub, Uc, Ud, Ue;
        float u1, u2, u3;     // E'-set after step0
        float v1, v2, v3;     // after step1
        float w1, w2, w3;     // after step2

        BH_STEP(es0, x1,  x2,  U,  e1,e2,e3, xt0, Ub, u1,u2,u3);
        BH_STEP(es1, xt0, x1,  Ub, u1,u2,u3, xt1, Uc, v1,v2,v3);
        BH_STEP(es2, xt1, xt0, Uc, v1,v2,v3, xt2, Ud, w1,w2,w3);
        BH_STEP(es3, xt2, xt1, Ud, w1,w2,w3, xt3, Ue, e1,e2,e3);

        x2 = xt2;
        x1 = xt3;
        U  = Ue;

        o4[i] = make_float4(xt0, xt1, xt2, xt3);
    }
}

extern "C" void kernel_launch(void* const* d_in, const int* in_sizes, int n_in,
                              void* d_out, int out_size)
{
    const float* theta = (const float*)d_in[0];   // (B, 11) float32
    const float* eps   = (const float*)d_in[1];   // (B, T)  float32
    float*       out   = (float*)d_out;           // (B, T)  float32

    bh_kernel<<<B_CONST / 32, 32>>>(theta, eps, out);
}